// round 10
// baseline (speedup 1.0000x reference)
#include <cuda_runtime.h>

#define DEGREE 20

// Rescaled Clenshaw evaluation of sum_k W_k * P_k(x), then * (1 - x^2).
//
//   d_k = cp_k + x d_{k+1} + g_k d_{k+2},  S = d_0
//   cp_k = W_k * C(2k,k)/2^k,  g_k = -(k+1)^2/((2k+1)(2k+3))  (literal)
//
// History:
// R1: 32-reg cap spilled cp[] (LDL in loop).            21.3us
// R3: occ==issue -> latency-bound (MLP=1).              22.6us
// R4: 4 chains + depth-1 prefetch, 4 blk/SM.            18.6us  issue 69.5%
// R7/R8: packed f32x2 -> FFMA2 rt~4 (64-bit banking),   18.5us  no win
// R9: 8 chains, 4 blk/SM -> issue 73.9%, SAME dur as R8's issue 40.9%
//     => DVFS active; FFMA-3reg measured rt~1 on B200 (128 fp32 lanes/SM);
//     binding resource is the issue port (~20k slots/SMSP), ~26% idle.
// R10: single-variable test: R4 body at 5 blocks/SM (launch_bounds(256,5),
//     grid 740). 10 warps/SMSP x 4 chains to close the issue gap.
//     Distinguishes issue-starved (dur -> ~15us) from power-pinned (dur
//     flat -> pivot to energy minimization).

__device__ __forceinline__ float legendre_eval(float xx, const float* __restrict__ cp) {
    float d1 = 0.0f, d2 = 0.0f;
#pragma unroll
    for (int k = DEGREE; k >= 0; --k) {
        float g = -(float)((k + 1) * (k + 1)) / (float)((2 * k + 1) * (2 * k + 3));
        float u = fmaf(g, d2, cp[k]);   // FFMA-imm
        float d0 = fmaf(xx, d1, u);     // FFMA 3-reg
        d2 = d1;
        d1 = d0;
    }
    float bc = fmaf(-xx, xx, 1.0f);     // 1 - x^2
    return d1 * bc;
}

__device__ __forceinline__ float4 eval4(float4 v, const float* __restrict__ cp) {
    float4 r;
    r.x = legendre_eval(v.x, cp);
    r.y = legendre_eval(v.y, cp);
    r.z = legendre_eval(v.z, cp);
    r.w = legendre_eval(v.w, cp);
    return r;
}

__global__ __launch_bounds__(256, 5) void legendre_kernel(
    const float* __restrict__ x, const float* __restrict__ W,
    float* __restrict__ out, int n)
{
    // Per-thread scaled coefficients: cp[k] = W[k] * M_k,
    // M_k = prod_{j=1..k} (2j-1)/j (ratios fold to immediates).
    float cp[DEGREE + 1];
    {
        float M = 1.0f;
        cp[0] = __ldg(&W[0]);
#pragma unroll
        for (int k = 1; k <= DEGREE; ++k) {
            M *= (float)(2 * k - 1) / (float)k;
            cp[k] = __ldg(&W[k]) * M;
        }
    }

    const int tid = blockIdx.x * blockDim.x + threadIdx.x;
    const int stride = gridDim.x * blockDim.x;
    const int n4 = n >> 2;

    const float4* __restrict__ x4 = (const float4*)x;
    float4* __restrict__ o4 = (float4*)out;

    // Depth-1 software pipeline: next LDG.128 issued before the current
    // ~170-instr Clenshaw block; 4 independent chains per warp-iteration.
    int i = tid;
    if (i < n4) {
        float4 v = x4[i];
        for (; i + stride < n4; i += stride) {
            float4 vn = x4[i + stride];   // prefetch
            o4[i] = eval4(v, cp);
            v = vn;
        }
        o4[i] = eval4(v, cp);
    }

    // Scalar tail (n % 4 != 0) — not hit for n = 8,000,000 but kept correct.
    for (int j = (n4 << 2) + tid; j < n; j += stride) {
        out[j] = legendre_eval(x[j], cp);
    }
}

extern "C" void kernel_launch(void* const* d_in, const int* in_sizes, int n_in,
                              void* d_out, int out_size) {
    // Identify W by its element count (DEGREE+1); x is the big array.
    const float* x = (const float*)d_in[0];
    const float* W = (const float*)d_in[1];
    if (n_in >= 2 && in_sizes[0] == DEGREE + 1 && in_sizes[1] != DEGREE + 1) {
        x = (const float*)d_in[1];
        W = (const float*)d_in[0];
    }
    float* out = (float*)d_out;
    int n = out_size;

    // 740 = exactly 5 resident blocks/SM on 148 SMs (51-reg budget; body
    // compiles to ~48). ~10.5 float4 iters/thread amortizes the prologue.
    legendre_kernel<<<740, 256>>>(x, W, out, n);
}